// round 7
// baseline (speedup 1.0000x reference)
#include <cuda_runtime.h>
#include <math.h>

#define BB 16
#define SS 4096
#define FF 512
#define NC 10
#define TABSZ 8192
#define TABM  8191
#define HEMPTY 0xFFFFFFFFu   // negative-NaN pattern; impossible after canonicalization

// global scratch
__device__ int   g_perm[BB * SS];
__device__ int   g_offs[BB * (NC + 1)];
__device__ float g_fin[BB * 15 * FF];     // [b][q][f]: q=0..4 stats, 5..14 class sums
__device__ int   g_uniq[BB * FF];

__device__ __forceinline__ unsigned hslot(unsigned x) {
    x *= 2654435761u;
    return (x >> 19) & TABM;
}

// ---------------------------------------------------------------------------
// Kernel 1: deterministic stable counting sort of y per batch (atomic-free)
// ---------------------------------------------------------------------------
__global__ void prep_kernel(const int* __restrict__ y) {
    __shared__ int histT[NC][256];
    __shared__ int curT[NC][256];
    __shared__ int offs[NC + 1];

    const int b = blockIdx.x;
    const int t = threadIdx.x;
    const int* yb = y + b * SS;
    const int base = t * 16;

#pragma unroll
    for (int c = 0; c < NC; c++) histT[c][t] = 0;
    __syncthreads();
#pragma unroll
    for (int j = 0; j < 16; j++) histT[yb[base + j]][t]++;
    __syncthreads();

    for (int d = 1; d < 256; d <<= 1) {
        int v[NC];
#pragma unroll
        for (int c = 0; c < NC; c++) v[c] = (t >= d) ? histT[c][t - d] : 0;
        __syncthreads();
#pragma unroll
        for (int c = 0; c < NC; c++) histT[c][t] += v[c];
        __syncthreads();
    }

    if (t == 0) {
        offs[0] = 0;
#pragma unroll
        for (int c = 0; c < NC; c++) offs[c + 1] = offs[c] + histT[c][255];
#pragma unroll
        for (int c = 0; c <= NC; c++) g_offs[b * (NC + 1) + c] = offs[c];
    }
    __syncthreads();
#pragma unroll
    for (int c = 0; c < NC; c++)
        curT[c][t] = offs[c] + (t > 0 ? histT[c][t - 1] : 0);
    __syncthreads();
#pragma unroll
    for (int j = 0; j < 16; j++) {
        int s = base + j;
        g_perm[b * SS + curT[yb[s]][t]++] = s;
    }
}

// ---------------------------------------------------------------------------
// Kernel 2: column kernel — grid (FF/4, BB), 512 threads, 2 CTAs/SM (carveout).
// Single X pass: stats + class sums + breadth-first barrier-verified hash.
// smem: vals planar [4][4096] f32 (64K) | tab[8192] u32 (32K) | red + misc
// ---------------------------------------------------------------------------
#define SM_VALS  0
#define SM_TAB   65536
#define SM_RED   (SM_TAB + 32768)        // 20*16 floats
#define SM_OFFS  (SM_RED + 1280)         // 12 ints
#define SM_CNT   (SM_OFFS + 48)          // 4 ints
#define CSMEM    (SM_CNT + 16)

__global__ void __launch_bounds__(512, 2)
column_kernel(const float* __restrict__ X) {
    extern __shared__ unsigned char sm[];
    float*    vals  = (float*)(sm + SM_VALS);
    unsigned* tab   = (unsigned*)(sm + SM_TAB);
    float*    red   = (float*)(sm + SM_RED);
    int*      soffs = (int*)(sm + SM_OFFS);
    int*      scnt  = (int*)(sm + SM_CNT);

    const int t  = threadIdx.x;
    const int fg = blockIdx.x, b = blockIdx.y;
    const int lane = t & 31, warp = t >> 5;

    if (t <= NC) soffs[t] = g_offs[b * (NC + 1) + t];
    if (t < 4)   scnt[t] = 0;

    // ----- Phase 1: load X once (8 independent LDG.128/thread) + 5 stats -----
    const float4* Xb = (const float4*)(X + (size_t)b * SS * FF);
    float s0[4] = {0,0,0,0}, s1[4] = {0,0,0,0}, s2[4] = {0,0,0,0};
    float s3[4] = {0,0,0,0}, s4[4] = {0,0,0,0};

#pragma unroll
    for (int k = 0; k < 8; k++) {
        const int s = k * 512 + t;
        const float4 x = __ldg(&Xb[(size_t)s * (FF / 4) + fg]);
        float xv[4] = {x.x, x.y, x.z, x.w};
#pragma unroll
        for (int f = 0; f < 4; f++) {
            float v = xv[f];
            const bool isn = (v != v);
            v = isn ? 0.f : v;
            v = (v == 0.f) ? 0.f : v;        // -0 -> +0
            const float a = fabsf(v);
            s0[f] += v;
            s1[f] += v * v;
            s2[f] += a;
            s3[f]  = fmaxf(s3[f], a);
            s4[f] += isn ? 1.f : 0.f;
            vals[f * SS + s] = v;            // planar layout
        }
    }

    // reduce the 20 class-independent stats
#pragma unroll
    for (int q = 0; q < 20; q++) {
        float v;
        if (q < 4)       v = s0[q];
        else if (q < 8)  v = s1[q - 4];
        else if (q < 12) v = s2[q - 8];
        else if (q < 16) v = s3[q - 12];
        else             v = s4[q - 16];
        const bool ismax = (q >= 12 && q < 16);
#pragma unroll
        for (int o = 16; o; o >>= 1) {
            float w = __shfl_xor_sync(0xFFFFFFFFu, v, o);
            v = ismax ? fmaxf(v, w) : (v + w);
        }
        if (lane == 0) red[q * 16 + warp] = v;
    }
    __syncthreads();
    if (t < 20) {
        const bool ismax = ((t >> 2) == 3);
        float v = red[t * 16];
#pragma unroll
        for (int w = 1; w < 16; w++)
            v = ismax ? fmaxf(v, red[t * 16 + w]) : (v + red[t * 16 + w]);
        g_fin[((size_t)b * 15 + (t >> 2)) * FF + fg * 4 + (t & 3)] = v;
    }

    // ----- Phase 2: per-class sums from smem in perm order (2 groups of 5) -----
    const int* perm = g_perm + b * SS;
#pragma unroll 1
    for (int grp = 0; grp < 2; grp++) {
        float cls[5][4];
#pragma unroll
        for (int c = 0; c < 5; c++)
#pragma unroll
            for (int f = 0; f < 4; f++) cls[c][f] = 0.f;

#pragma unroll
        for (int c = 0; c < 5; c++) {
            const int cc = grp * 5 + c;
            const int lo = soffs[cc], hi = soffs[cc + 1];
            for (int i = lo + t; i < hi; i += 512) {
                const int s = __ldg(&perm[i]);
#pragma unroll
                for (int f = 0; f < 4; f++) cls[c][f] += vals[f * SS + s];
            }
        }
#pragma unroll
        for (int q = 0; q < 20; q++) {
            float v = cls[q >> 2][q & 3];
#pragma unroll
            for (int o = 16; o; o >>= 1)
                v += __shfl_xor_sync(0xFFFFFFFFu, v, o);
            if (lane == 0) red[q * 16 + warp] = v;
        }
        __syncthreads();
        if (t < 20) {
            float v = red[t * 16];
#pragma unroll
            for (int w = 1; w < 16; w++) v += red[t * 16 + w];
            const int c = grp * 5 + (t >> 2);
            g_fin[((size_t)b * 15 + 5 + c) * FF + fg * 4 + (t & 3)] = v;
        }
        __syncthreads();
    }

    // ----- Phase 3: exact unique count, breadth-first barrier-verified hash -----
#pragma unroll 1
    for (int f = 0; f < 4; f++) {
#pragma unroll
        for (int k = 0; k < TABSZ / 512; k++) tab[k * 512 + t] = HEMPTY;

        unsigned v[8];
        int p[8];
#pragma unroll
        for (int k = 0; k < 8; k++) {
            v[k] = __float_as_uint(vals[f * SS + k * 512 + t]);
            p[k] = hslot(v[k]);
        }
        __syncthreads();                 // table init visible
#pragma unroll
        for (int k = 0; k < 8; k++) tab[p[k]] = v[k];   // round 0: blind write

        unsigned mask = 0xFFu;
        while (__syncthreads_or((int)mask)) {           // prior writes stable
            unsigned wm = 0, pend = mask;
            while (pend) {
                unsigned u[8];
#pragma unroll
                for (int k = 0; k < 8; k++)             // batched independent LDS
                    if (pend & (1u << k)) u[k] = tab[p[k]];
#pragma unroll
                for (int k = 0; k < 8; k++) {
                    if (pend & (1u << k)) {
                        if (u[k] == v[k])       { mask &= ~(1u << k); pend &= ~(1u << k); }
                        else if (u[k] == HEMPTY){ wm   |=  (1u << k); pend &= ~(1u << k); }
                        else p[k] = (p[k] + 1) & TABM;
                    }
                }
            }
            __syncthreads();             // all reads done before writes
#pragma unroll
            for (int k = 0; k < 8; k++)
                if (wm & (1u << k)) tab[p[k]] = v[k];
        }

        int cnt = 0;
#pragma unroll
        for (int k = 0; k < TABSZ / 512; k++) cnt += (tab[k * 512 + t] != HEMPTY);
#pragma unroll
        for (int o = 16; o; o >>= 1) cnt += __shfl_xor_sync(0xFFFFFFFFu, cnt, o);
        if (lane == 0) atomicAdd(&scnt[f], cnt);
        __syncthreads();                 // counts read before next table re-init
    }
    if (t < 4) g_uniq[b * FF + fg * 4 + t] = scnt[t];
}

// ---------------------------------------------------------------------------
// Kernel 3: stats assembly + MLP. Grid (16, 16), 256 threads, 32 feat/CTA.
// ---------------------------------------------------------------------------
#define MS_RED  0
#define MS_SST  (MS_RED + 15 * 32 * 4)        // 1920
#define MS_H    (MS_SST + 32 * 8 * 4)         // +1024
#define MS_W2   (MS_H + 32 * 64 * 4)          // +8192
#define MS_OFF  (MS_W2 + 64 * 128 * 4)        // +32768
#define MSMEM   (MS_OFF + 64)

__global__ void __launch_bounds__(256)
mlp_kernel(const float* __restrict__ w1, const float* __restrict__ b1,
           const float* __restrict__ w2, const float* __restrict__ b2,
           float* __restrict__ out) {
    extern __shared__ unsigned char sm[];
    float* sred  = (float*)(sm + MS_RED);    // [15][32]
    float* sst   = (float*)(sm + MS_SST);    // [32][8]
    float* sh    = (float*)(sm + MS_H);      // [32][64]
    float* sw2   = (float*)(sm + MS_W2);     // [64][128]
    int*   soffs = (int*)(sm + MS_OFF);

    const int t    = threadIdx.x;
    const int tile = blockIdx.x, b = blockIdx.y;

    if (t <= NC) soffs[t] = g_offs[b * (NC + 1) + t];
#pragma unroll
    for (int k = 0; k < 32; k++) sw2[k * 256 + t] = __ldg(&w2[k * 256 + t]);

    for (int idx = t; idx < 480; idx += 256) {
        const int qq = idx >> 5, fl = idx & 31;
        sred[qq * 32 + fl] =
            __ldg(&g_fin[((size_t)b * 15 + qq) * FF + tile * 32 + fl]);
    }
    __syncthreads();

    if (t < 32) {
        const int fl = t;
        const float Sf = (float)SS;
        const float sum    = sred[0 * 32 + fl];
        const float sumsq  = sred[1 * 32 + fl];
        const float sumabs = sred[2 * 32 + fl];
        const float mx     = sred[3 * 32 + fl];
        const float nanc   = sred[4 * 32 + fl];
        const float g   = sum / Sf;
        const float var = sumsq / Sf - g * g;
        float between = 0.f;
#pragma unroll
        for (int c = 0; c < NC; c++) {
            const float cntc = (float)(soffs[c + 1] - soffs[c]);
            const float cm = sred[(5 + c) * 32 + fl] / fmaxf(cntc, 1.f);
            const float d = cm - g;
            between += cntc * d * d;
        }
        between /= Sf;
        float st[6];
        st[0] = between / fmaxf(var, 1e-6f);
        st[1] = nanc / Sf;
        st[2] = (float)__ldg(&g_uniq[b * FF + tile * 32 + fl]) / Sf;
        st[3] = var;
        st[4] = sumabs / Sf;
        st[5] = mx;
#pragma unroll
        for (int k = 0; k < 6; k++) {
            float v = st[k];
            if (!isfinite(v)) v = 0.f;
            sst[fl * 8 + k] = v;
        }
    }
    __syncthreads();

    // hidden: 32 x 64 = 2048 over 256 threads
#pragma unroll
    for (int r = 0; r < 8; r++) {
        const int idx = r * 256 + t;
        const int f = idx >> 6, j = idx & 63;
        float z = __ldg(&b1[j]);
#pragma unroll
        for (int i = 0; i < 6; i++) z += sst[f * 8 + i] * __ldg(&w1[i * 64 + j]);
        sh[idx] = z * normcdff(z);           // exact GELU
    }
    __syncthreads();

    // output: 32 x 128 = 4096 over 256 threads
#pragma unroll
    for (int r = 0; r < 16; r++) {
        const int idx = r * 256 + t;
        const int f = idx >> 7, o = idx & 127;
        float z0 = 0.f, z1 = 0.f;
#pragma unroll 16
        for (int j = 0; j < 64; j += 2) {
            z0 += sh[f * 64 + j]     * sw2[j * 128 + o];
            z1 += sh[f * 64 + j + 1] * sw2[(j + 1) * 128 + o];
        }
        out[((size_t)(b * FF) + tile * 32 + f) * 128 + o] =
            z0 + z1 + __ldg(&b2[o]);
    }
}

// ---------------------------------------------------------------------------
extern "C" void kernel_launch(void* const* d_in, const int* in_sizes, int n_in,
                              void* d_out, int out_size) {
    const float* X  = (const float*)d_in[0];
    const int*   y  = (const int*)d_in[1];
    const float* w1 = (const float*)d_in[2];
    const float* b1 = (const float*)d_in[3];
    const float* w2 = (const float*)d_in[4];
    const float* b2 = (const float*)d_in[5];
    float* out = (float*)d_out;

    cudaFuncSetAttribute(column_kernel,
                         cudaFuncAttributeMaxDynamicSharedMemorySize, CSMEM);
    // Request max smem carveout so two ~98KB CTAs can co-reside per SM.
    cudaFuncSetAttribute(column_kernel,
                         cudaFuncAttributePreferredSharedMemoryCarveout, 100);
    cudaFuncSetAttribute(mlp_kernel,
                         cudaFuncAttributeMaxDynamicSharedMemorySize, MSMEM);

    prep_kernel<<<BB, 256>>>(y);
    column_kernel<<<dim3(FF / 4, BB), 512, CSMEM>>>(X);
    mlp_kernel<<<dim3(16, BB), 256, MSMEM>>>(w1, b1, w2, b2, out);
}

// round 8
// speedup vs baseline: 1.1558x; 1.1558x over previous
#include <cuda_runtime.h>
#include <math.h>

#define BB 16
#define SS 4096
#define FF 512
#define NC 10
#define TABSZ 8192
#define TABM  8191
#define HEMPTY 0xFFFFFFFFu   // negative-NaN pattern; impossible after canonicalization

// global scratch
__device__ int   g_perm[BB * SS];
__device__ int   g_offs[BB * (NC + 1)];
__device__ float g_fin[BB * 15 * FF];     // [b][q][f]: q=0..4 stats, 5..14 class sums
__device__ int   g_uniq[BB * FF];

__device__ __forceinline__ unsigned hslot(unsigned x) {
    x *= 2654435761u;
    return (x >> 19) & TABM;
}

// ---------------------------------------------------------------------------
// Kernel 1: deterministic stable counting sort of y per batch (atomic-free)
// ---------------------------------------------------------------------------
__global__ void prep_kernel(const int* __restrict__ y) {
    __shared__ int histT[NC][256];
    __shared__ int curT[NC][256];
    __shared__ int offs[NC + 1];

    const int b = blockIdx.x;
    const int t = threadIdx.x;
    const int* yb = y + b * SS;
    const int base = t * 16;

#pragma unroll
    for (int c = 0; c < NC; c++) histT[c][t] = 0;
    __syncthreads();
#pragma unroll
    for (int j = 0; j < 16; j++) histT[yb[base + j]][t]++;
    __syncthreads();

    for (int d = 1; d < 256; d <<= 1) {
        int v[NC];
#pragma unroll
        for (int c = 0; c < NC; c++) v[c] = (t >= d) ? histT[c][t - d] : 0;
        __syncthreads();
#pragma unroll
        for (int c = 0; c < NC; c++) histT[c][t] += v[c];
        __syncthreads();
    }

    if (t == 0) {
        offs[0] = 0;
#pragma unroll
        for (int c = 0; c < NC; c++) offs[c + 1] = offs[c] + histT[c][255];
#pragma unroll
        for (int c = 0; c <= NC; c++) g_offs[b * (NC + 1) + c] = offs[c];
    }
    __syncthreads();
#pragma unroll
    for (int c = 0; c < NC; c++)
        curT[c][t] = offs[c] + (t > 0 ? histT[c][t - 1] : 0);
    __syncthreads();
#pragma unroll
    for (int j = 0; j < 16; j++) {
        int s = base + j;
        g_perm[b * SS + curT[yb[s]][t]++] = s;
    }
}

// ---------------------------------------------------------------------------
// Kernel 2: column kernel — grid (FF/4, BB), 512 threads.
// Single X pass: stats + class sums + HYBRID unique count:
//   blind non-atomic write round resolves ~70-75% of inserts with 0 atomics;
//   only losers run a read-then-CAS probe loop (~1 CAS each).
// smem: vals planar [4][4096] f32 (64K) | tab[8192] u32 (32K) | red + misc
// ---------------------------------------------------------------------------
#define SM_VALS  0
#define SM_TAB   65536
#define SM_RED   (SM_TAB + 32768)        // 20*16 floats
#define SM_OFFS  (SM_RED + 1280)         // 12 ints
#define SM_CNT   (SM_OFFS + 48)          // 4 ints
#define CSMEM    (SM_CNT + 16)

__global__ void __launch_bounds__(512, 2)
column_kernel(const float* __restrict__ X) {
    extern __shared__ unsigned char sm[];
    float*    vals  = (float*)(sm + SM_VALS);
    unsigned* tab   = (unsigned*)(sm + SM_TAB);
    float*    red   = (float*)(sm + SM_RED);
    int*      soffs = (int*)(sm + SM_OFFS);
    int*      scnt  = (int*)(sm + SM_CNT);

    const int t  = threadIdx.x;
    const int fg = blockIdx.x, b = blockIdx.y;
    const int lane = t & 31, warp = t >> 5;

    if (t <= NC) soffs[t] = g_offs[b * (NC + 1) + t];
    if (t < 4)   scnt[t] = 0;

    // ----- Phase 1: load X once (8 independent LDG.128/thread) + 5 stats -----
    const float4* Xb = (const float4*)(X + (size_t)b * SS * FF);
    float s0[4] = {0,0,0,0}, s1[4] = {0,0,0,0}, s2[4] = {0,0,0,0};
    float s3[4] = {0,0,0,0}, s4[4] = {0,0,0,0};

#pragma unroll
    for (int k = 0; k < 8; k++) {
        const int s = k * 512 + t;
        const float4 x = __ldg(&Xb[(size_t)s * (FF / 4) + fg]);
        float xv[4] = {x.x, x.y, x.z, x.w};
#pragma unroll
        for (int f = 0; f < 4; f++) {
            float v = xv[f];
            const bool isn = (v != v);
            v = isn ? 0.f : v;
            v = (v == 0.f) ? 0.f : v;        // -0 -> +0
            const float a = fabsf(v);
            s0[f] += v;
            s1[f] += v * v;
            s2[f] += a;
            s3[f]  = fmaxf(s3[f], a);
            s4[f] += isn ? 1.f : 0.f;
            vals[f * SS + s] = v;            // planar layout
        }
    }

    // reduce the 20 class-independent stats
#pragma unroll
    for (int q = 0; q < 20; q++) {
        float v;
        if (q < 4)       v = s0[q];
        else if (q < 8)  v = s1[q - 4];
        else if (q < 12) v = s2[q - 8];
        else if (q < 16) v = s3[q - 12];
        else             v = s4[q - 16];
        const bool ismax = (q >= 12 && q < 16);
#pragma unroll
        for (int o = 16; o; o >>= 1) {
            float w = __shfl_xor_sync(0xFFFFFFFFu, v, o);
            v = ismax ? fmaxf(v, w) : (v + w);
        }
        if (lane == 0) red[q * 16 + warp] = v;
    }
    __syncthreads();
    if (t < 20) {
        const bool ismax = ((t >> 2) == 3);
        float v = red[t * 16];
#pragma unroll
        for (int w = 1; w < 16; w++)
            v = ismax ? fmaxf(v, red[t * 16 + w]) : (v + red[t * 16 + w]);
        g_fin[((size_t)b * 15 + (t >> 2)) * FF + fg * 4 + (t & 3)] = v;
    }

    // ----- Phase 2: per-class sums from smem in perm order (2 groups of 5) -----
    const int* perm = g_perm + b * SS;
#pragma unroll 1
    for (int grp = 0; grp < 2; grp++) {
        float cls[5][4];
#pragma unroll
        for (int c = 0; c < 5; c++)
#pragma unroll
            for (int f = 0; f < 4; f++) cls[c][f] = 0.f;

#pragma unroll
        for (int c = 0; c < 5; c++) {
            const int cc = grp * 5 + c;
            const int lo = soffs[cc], hi = soffs[cc + 1];
            for (int i = lo + t; i < hi; i += 512) {
                const int s = __ldg(&perm[i]);
#pragma unroll
                for (int f = 0; f < 4; f++) cls[c][f] += vals[f * SS + s];
            }
        }
#pragma unroll
        for (int q = 0; q < 20; q++) {
            float v = cls[q >> 2][q & 3];
#pragma unroll
            for (int o = 16; o; o >>= 1)
                v += __shfl_xor_sync(0xFFFFFFFFu, v, o);
            if (lane == 0) red[q * 16 + warp] = v;
        }
        __syncthreads();
        if (t < 20) {
            float v = red[t * 16];
#pragma unroll
            for (int w = 1; w < 16; w++) v += red[t * 16 + w];
            const int c = grp * 5 + (t >> 2);
            g_fin[((size_t)b * 15 + 5 + c) * FF + fg * 4 + (t & 3)] = v;
        }
        __syncthreads();
    }

    // ----- Phase 3: hybrid exact unique count per feature -----
#pragma unroll 1
    for (int f = 0; f < 4; f++) {
#pragma unroll
        for (int k = 0; k < TABSZ / 512; k++) tab[k * 512 + t] = HEMPTY;

        unsigned v[8];
        int h[8];
#pragma unroll
        for (int k = 0; k < 8; k++) {
            v[k] = __float_as_uint(vals[f * SS + k * 512 + t]);
            h[k] = hslot(v[k]);
        }
        __syncthreads();                 // table init visible

        // Round 0: blind non-atomic writes (one winner per contested slot)
#pragma unroll
        for (int k = 0; k < 8; k++) tab[h[k]] = v[k];
        __syncthreads();                 // blind writes stable

        // Verify; losers do read-then-CAS probe insert (exact, ~1 CAS each)
#pragma unroll
        for (int k = 0; k < 8; k++) {
            if (tab[h[k]] != v[k]) {
                int p = (h[k] + 1) & TABM;
                for (;;) {
                    const unsigned u = tab[p];
                    if (u == v[k]) break;
                    if (u == HEMPTY) {
                        const unsigned old = atomicCAS(&tab[p], HEMPTY, v[k]);
                        if (old == HEMPTY || old == v[k]) break;
                        // other value claimed it; treat as occupied, advance
                    }
                    p = (p + 1) & TABM;
                }
            }
        }
        __syncthreads();                 // all inserts done

        int cnt = 0;
#pragma unroll
        for (int k = 0; k < TABSZ / 512; k++) cnt += (tab[k * 512 + t] != HEMPTY);
#pragma unroll
        for (int o = 16; o; o >>= 1) cnt += __shfl_xor_sync(0xFFFFFFFFu, cnt, o);
        if (lane == 0) atomicAdd(&scnt[f], cnt);
        __syncthreads();                 // counts read before next re-init
    }
    if (t < 4) g_uniq[b * FF + fg * 4 + t] = scnt[t];
}

// ---------------------------------------------------------------------------
// Kernel 3: stats assembly + MLP. Grid (16, 16), 256 threads, 32 feat/CTA.
// ---------------------------------------------------------------------------
#define MS_RED  0
#define MS_SST  (MS_RED + 15 * 32 * 4)        // 1920
#define MS_H    (MS_SST + 32 * 8 * 4)         // +1024
#define MS_W2   (MS_H + 32 * 64 * 4)          // +8192
#define MS_OFF  (MS_W2 + 64 * 128 * 4)        // +32768
#define MSMEM   (MS_OFF + 64)

__global__ void __launch_bounds__(256)
mlp_kernel(const float* __restrict__ w1, const float* __restrict__ b1,
           const float* __restrict__ w2, const float* __restrict__ b2,
           float* __restrict__ out) {
    extern __shared__ unsigned char sm[];
    float* sred  = (float*)(sm + MS_RED);    // [15][32]
    float* sst   = (float*)(sm + MS_SST);    // [32][8]
    float* sh    = (float*)(sm + MS_H);      // [32][64]
    float* sw2   = (float*)(sm + MS_W2);     // [64][128]
    int*   soffs = (int*)(sm + MS_OFF);

    const int t    = threadIdx.x;
    const int tile = blockIdx.x, b = blockIdx.y;

    if (t <= NC) soffs[t] = g_offs[b * (NC + 1) + t];
#pragma unroll
    for (int k = 0; k < 32; k++) sw2[k * 256 + t] = __ldg(&w2[k * 256 + t]);

    for (int idx = t; idx < 480; idx += 256) {
        const int qq = idx >> 5, fl = idx & 31;
        sred[qq * 32 + fl] =
            __ldg(&g_fin[((size_t)b * 15 + qq) * FF + tile * 32 + fl]);
    }
    __syncthreads();

    if (t < 32) {
        const int fl = t;
        const float Sf = (float)SS;
        const float sum    = sred[0 * 32 + fl];
        const float sumsq  = sred[1 * 32 + fl];
        const float sumabs = sred[2 * 32 + fl];
        const float mx     = sred[3 * 32 + fl];
        const float nanc   = sred[4 * 32 + fl];
        const float g   = sum / Sf;
        const float var = sumsq / Sf - g * g;
        float between = 0.f;
#pragma unroll
        for (int c = 0; c < NC; c++) {
            const float cntc = (float)(soffs[c + 1] - soffs[c]);
            const float cm = sred[(5 + c) * 32 + fl] / fmaxf(cntc, 1.f);
            const float d = cm - g;
            between += cntc * d * d;
        }
        between /= Sf;
        float st[6];
        st[0] = between / fmaxf(var, 1e-6f);
        st[1] = nanc / Sf;
        st[2] = (float)__ldg(&g_uniq[b * FF + tile * 32 + fl]) / Sf;
        st[3] = var;
        st[4] = sumabs / Sf;
        st[5] = mx;
#pragma unroll
        for (int k = 0; k < 6; k++) {
            float v = st[k];
            if (!isfinite(v)) v = 0.f;
            sst[fl * 8 + k] = v;
        }
    }
    __syncthreads();

    // hidden: 32 x 64 = 2048 over 256 threads
#pragma unroll
    for (int r = 0; r < 8; r++) {
        const int idx = r * 256 + t;
        const int f = idx >> 6, j = idx & 63;
        float z = __ldg(&b1[j]);
#pragma unroll
        for (int i = 0; i < 6; i++) z += sst[f * 8 + i] * __ldg(&w1[i * 64 + j]);
        sh[idx] = z * normcdff(z);           // exact GELU
    }
    __syncthreads();

    // output: 32 x 128 = 4096 over 256 threads
#pragma unroll
    for (int r = 0; r < 16; r++) {
        const int idx = r * 256 + t;
        const int f = idx >> 7, o = idx & 127;
        float z0 = 0.f, z1 = 0.f;
#pragma unroll 16
        for (int j = 0; j < 64; j += 2) {
            z0 += sh[f * 64 + j]     * sw2[j * 128 + o];
            z1 += sh[f * 64 + j + 1] * sw2[(j + 1) * 128 + o];
        }
        out[((size_t)(b * FF) + tile * 32 + f) * 128 + o] =
            z0 + z1 + __ldg(&b2[o]);
    }
}

// ---------------------------------------------------------------------------
extern "C" void kernel_launch(void* const* d_in, const int* in_sizes, int n_in,
                              void* d_out, int out_size) {
    const float* X  = (const float*)d_in[0];
    const int*   y  = (const int*)d_in[1];
    const float* w1 = (const float*)d_in[2];
    const float* b1 = (const float*)d_in[3];
    const float* w2 = (const float*)d_in[4];
    const float* b2 = (const float*)d_in[5];
    float* out = (float*)d_out;

    cudaFuncSetAttribute(column_kernel,
                         cudaFuncAttributeMaxDynamicSharedMemorySize, CSMEM);
    cudaFuncSetAttribute(column_kernel,
                         cudaFuncAttributePreferredSharedMemoryCarveout, 100);
    cudaFuncSetAttribute(mlp_kernel,
                         cudaFuncAttributeMaxDynamicSharedMemorySize, MSMEM);

    prep_kernel<<<BB, 256>>>(y);
    column_kernel<<<dim3(FF / 4, BB), 512, CSMEM>>>(X);
    mlp_kernel<<<dim3(16, BB), 256, MSMEM>>>(w1, b1, w2, b2, out);
}

// round 10
// speedup vs baseline: 1.8587x; 1.6081x over previous
#include <cuda_runtime.h>
#include <math.h>

#define BB 16
#define SS 4096
#define FF 512
#define NC 10
#define TABSZ 8192
#define TABM  8191
#define HEMPTY 0xFFFFFFFFu   // negative-NaN pattern; impossible after canonicalization

// global scratch (static device arrays; no allocation)
__device__ int   g_perm[BB * SS];
__device__ int   g_offs[BB * (NC + 1)];
__device__ float g_fin[BB * 15 * FF];          // [b][q][f]
__device__ int   g_uniq[BB * FF];
__device__ float g_cols[(size_t)BB * FF * SS]; // transposed canonical columns

__device__ __forceinline__ unsigned hslot(unsigned x) {
    x *= 2654435761u;
    return (x >> 19) & TABM;
}

// ---------------------------------------------------------------------------
// Kernel 1: deterministic stable counting sort of y per batch (atomic-free)
// ---------------------------------------------------------------------------
__global__ void prep_kernel(const int* __restrict__ y) {
    __shared__ int histT[NC][256];
    __shared__ int curT[NC][256];
    __shared__ int offs[NC + 1];

    const int b = blockIdx.x;
    const int t = threadIdx.x;
    const int* yb = y + b * SS;
    const int base = t * 16;

#pragma unroll
    for (int c = 0; c < NC; c++) histT[c][t] = 0;
    __syncthreads();
#pragma unroll
    for (int j = 0; j < 16; j++) histT[yb[base + j]][t]++;
    __syncthreads();

    for (int d = 1; d < 256; d <<= 1) {
        int v[NC];
#pragma unroll
        for (int c = 0; c < NC; c++) v[c] = (t >= d) ? histT[c][t - d] : 0;
        __syncthreads();
#pragma unroll
        for (int c = 0; c < NC; c++) histT[c][t] += v[c];
        __syncthreads();
    }

    if (t == 0) {
        offs[0] = 0;
#pragma unroll
        for (int c = 0; c < NC; c++) offs[c + 1] = offs[c] + histT[c][255];
#pragma unroll
        for (int c = 0; c <= NC; c++) g_offs[b * (NC + 1) + c] = offs[c];
    }
    __syncthreads();
#pragma unroll
    for (int c = 0; c < NC; c++)
        curT[c][t] = offs[c] + (t > 0 ? histT[c][t - 1] : 0);
    __syncthreads();
#pragma unroll
    for (int j = 0; j < 16; j++) {
        int s = base + j;
        g_perm[b * SS + curT[yb[s]][t]++] = s;
    }
}

// ---------------------------------------------------------------------------
// Kernel 2: stats kernel — grid (FF/4, BB), 256 threads, 3 CTAs/SM.
// Single X pass: 5 stats + class sums; writes canonical columns to g_cols.
// smem: vals planar [4][4096] f32 (64K) + red/offs (no hash table)
// ---------------------------------------------------------------------------
#define SM_VALS 0
#define SM_RED  65536                    // 20*8 floats
#define SM_OFFS (SM_RED + 640)           // 12 ints
#define SSMEM   (SM_OFFS + 48)

__global__ void __launch_bounds__(256, 3)
stats_kernel(const float* __restrict__ X) {
    extern __shared__ unsigned char sm[];
    float* vals  = (float*)(sm + SM_VALS);
    float* red   = (float*)(sm + SM_RED);
    int*   soffs = (int*)(sm + SM_OFFS);

    const int t  = threadIdx.x;
    const int fg = blockIdx.x, b = blockIdx.y;
    const int lane = t & 31, warp = t >> 5;

    if (t <= NC) soffs[t] = g_offs[b * (NC + 1) + t];

    // ----- Phase 1: load X once (16 independent LDG.128/thread) + 5 stats -----
    const float4* Xb = (const float4*)(X + (size_t)b * SS * FF);
    float s0[4] = {0,0,0,0}, s1[4] = {0,0,0,0}, s2[4] = {0,0,0,0};
    float s3[4] = {0,0,0,0}, s4[4] = {0,0,0,0};

#pragma unroll
    for (int k = 0; k < 16; k++) {
        const int s = k * 256 + t;
        const float4 x = __ldg(&Xb[(size_t)s * (FF / 4) + fg]);
        float xv[4] = {x.x, x.y, x.z, x.w};
#pragma unroll
        for (int f = 0; f < 4; f++) {
            float v = xv[f];
            const bool isn = (v != v);
            v = isn ? 0.f : v;
            v = (v == 0.f) ? 0.f : v;        // -0 -> +0
            const float a = fabsf(v);
            s0[f] += v;
            s1[f] += v * v;
            s2[f] += a;
            s3[f]  = fmaxf(s3[f], a);
            s4[f] += isn ? 1.f : 0.f;
            vals[f * SS + s] = v;
        }
    }

    // reduce 20 class-independent stats
#pragma unroll
    for (int q = 0; q < 20; q++) {
        float v;
        if (q < 4)       v = s0[q];
        else if (q < 8)  v = s1[q - 4];
        else if (q < 12) v = s2[q - 8];
        else if (q < 16) v = s3[q - 12];
        else             v = s4[q - 16];
        const bool ismax = (q >= 12 && q < 16);
#pragma unroll
        for (int o = 16; o; o >>= 1) {
            float w = __shfl_xor_sync(0xFFFFFFFFu, v, o);
            v = ismax ? fmaxf(v, w) : (v + w);
        }
        if (lane == 0) red[q * 8 + warp] = v;
    }
    __syncthreads();
    if (t < 20) {
        const bool ismax = ((t >> 2) == 3);
        float v = red[t * 8];
#pragma unroll
        for (int w = 1; w < 8; w++)
            v = ismax ? fmaxf(v, red[t * 8 + w]) : (v + red[t * 8 + w]);
        g_fin[((size_t)b * 15 + (t >> 2)) * FF + fg * 4 + (t & 3)] = v;
    }

    // ----- Phase 2: write transposed canonical columns (coalesced) -----
#pragma unroll
    for (int f = 0; f < 4; f++) {
        float4*       dst = (float4*)(g_cols + ((size_t)b * FF + fg * 4 + f) * SS);
        const float4* src = (const float4*)(vals + f * SS);
#pragma unroll
        for (int k = 0; k < 4; k++) dst[k * 256 + t] = src[k * 256 + t];
    }

    // ----- Phase 3: per-class sums from smem in perm order (2 groups of 5) -----
    const int* perm = g_perm + b * SS;
#pragma unroll 1
    for (int grp = 0; grp < 2; grp++) {
        float cls[5][4];
#pragma unroll
        for (int c = 0; c < 5; c++)
#pragma unroll
            for (int f = 0; f < 4; f++) cls[c][f] = 0.f;

#pragma unroll
        for (int c = 0; c < 5; c++) {
            const int cc = grp * 5 + c;
            const int lo = soffs[cc], hi = soffs[cc + 1];
            for (int i = lo + t; i < hi; i += 256) {
                const int s = __ldg(&perm[i]);
#pragma unroll
                for (int f = 0; f < 4; f++) cls[c][f] += vals[f * SS + s];
            }
        }
#pragma unroll
        for (int q = 0; q < 20; q++) {
            float v = cls[q >> 2][q & 3];
#pragma unroll
            for (int o = 16; o; o >>= 1)
                v += __shfl_xor_sync(0xFFFFFFFFu, v, o);
            if (lane == 0) red[q * 8 + warp] = v;
        }
        __syncthreads();
        if (t < 20) {
            float v = red[t * 8];
#pragma unroll
            for (int w = 1; w < 8; w++) v += red[t * 8 + w];
            const int c = grp * 5 + (t >> 2);
            g_fin[((size_t)b * 15 + 5 + c) * FF + fg * 4 + (t & 3)] = v;
        }
        __syncthreads();
    }
}

// ---------------------------------------------------------------------------
// Kernel 3: uniq kernel — one CTA per (f, b), 256 threads, 33KB smem,
// 6 CTAs/SM. Non-atomic blind-write + verify-scan rounds; exact count.
// ---------------------------------------------------------------------------
#define USMEM (TABSZ * 4 + 16)

__global__ void __launch_bounds__(256, 6)
uniq_kernel() {
    extern __shared__ unsigned char sm[];
    unsigned* tab  = (unsigned*)sm;
    int*      scnt = (int*)(sm + TABSZ * 4);

    const int t = threadIdx.x;
    const int f = blockIdx.x, b = blockIdx.y;
    const float4* col4 = (const float4*)(g_cols + ((size_t)b * FF + f) * SS);

#pragma unroll
    for (int k = 0; k < TABSZ / 256; k++) tab[k * 256 + t] = HEMPTY;
    if (t == 0) scnt[0] = 0;

#pragma unroll 1
    for (int half = 0; half < 2; half++) {
        // 8 values per thread, coalesced
        unsigned v[8];
        int p[8];
#pragma unroll
        for (int k = 0; k < 2; k++) {
            const float4 x = __ldg(&col4[half * 512 + k * 256 + t]);
            v[k * 4 + 0] = __float_as_uint(x.x);
            v[k * 4 + 1] = __float_as_uint(x.y);
            v[k * 4 + 2] = __float_as_uint(x.z);
            v[k * 4 + 3] = __float_as_uint(x.w);
        }
#pragma unroll
        for (int k = 0; k < 8; k++) p[k] = hslot(v[k]);
        __syncthreads();                 // table state stable (init or half 0 done)

        if (half == 0) {                 // blind round only on empty table
#pragma unroll
            for (int k = 0; k < 8; k++) tab[p[k]] = v[k];
        }

        unsigned mask = 0xFFu;
        while (__syncthreads_or((int)mask)) {     // prior writes stable
            unsigned wm = 0;
#pragma unroll
            for (int k = 0; k < 8; k++) {
                if (mask & (1u << k)) {
                    int pp = p[k];
                    for (;;) {                    // scan stable snapshot
                        const unsigned u = tab[pp];
                        if (u == v[k]) { mask &= ~(1u << k); break; }
                        if (u == HEMPTY) { wm |= 1u << k; break; }
                        pp = (pp + 1) & TABM;
                    }
                    p[k] = pp;
                }
            }
            __syncthreads();                      // reads done before writes
#pragma unroll
            for (int k = 0; k < 8; k++)           // writes target EMPTY slots only
                if (wm & (1u << k)) tab[p[k]] = v[k];
        }
    }

    int cnt = 0;
#pragma unroll
    for (int k = 0; k < TABSZ / (256 * 4); k++) {
        const uint4 u = ((const uint4*)tab)[k * 256 + t];
        cnt += (u.x != HEMPTY) + (u.y != HEMPTY) + (u.z != HEMPTY) + (u.w != HEMPTY);
    }
#pragma unroll
    for (int o = 16; o; o >>= 1) cnt += __shfl_xor_sync(0xFFFFFFFFu, cnt, o);
    if ((t & 31) == 0) atomicAdd(&scnt[0], cnt);
    __syncthreads();
    if (t == 0) g_uniq[b * FF + f] = scnt[0];
}

// ---------------------------------------------------------------------------
// Kernel 4: stats assembly + MLP. Grid (16, 16), 256 threads, 32 feat/CTA.
// ---------------------------------------------------------------------------
#define MS_RED  0
#define MS_SST  (MS_RED + 15 * 32 * 4)        // 1920
#define MS_H    (MS_SST + 32 * 8 * 4)         // +1024
#define MS_W2   (MS_H + 32 * 64 * 4)          // +8192
#define MS_OFF  (MS_W2 + 64 * 128 * 4)        // +32768
#define MSMEM   (MS_OFF + 64)

__global__ void __launch_bounds__(256)
mlp_kernel(const float* __restrict__ w1, const float* __restrict__ b1,
           const float* __restrict__ w2, const float* __restrict__ b2,
           float* __restrict__ out) {
    extern __shared__ unsigned char sm[];
    float* sred  = (float*)(sm + MS_RED);
    float* sst   = (float*)(sm + MS_SST);
    float* sh    = (float*)(sm + MS_H);
    float* sw2   = (float*)(sm + MS_W2);
    int*   soffs = (int*)(sm + MS_OFF);

    const int t    = threadIdx.x;
    const int tile = blockIdx.x, b = blockIdx.y;

    if (t <= NC) soffs[t] = g_offs[b * (NC + 1) + t];
#pragma unroll
    for (int k = 0; k < 32; k++) sw2[k * 256 + t] = __ldg(&w2[k * 256 + t]);

    for (int idx = t; idx < 480; idx += 256) {
        const int qq = idx >> 5, fl = idx & 31;
        sred[qq * 32 + fl] =
            __ldg(&g_fin[((size_t)b * 15 + qq) * FF + tile * 32 + fl]);
    }
    __syncthreads();

    if (t < 32) {
        const int fl = t;
        const float Sf = (float)SS;
        const float sum    = sred[0 * 32 + fl];
        const float sumsq  = sred[1 * 32 + fl];
        const float sumabs = sred[2 * 32 + fl];
        const float mx     = sred[3 * 32 + fl];
        const float nanc   = sred[4 * 32 + fl];
        const float g   = sum / Sf;
        const float var = sumsq / Sf - g * g;
        float between = 0.f;
#pragma unroll
        for (int c = 0; c < NC; c++) {
            const float cntc = (float)(soffs[c + 1] - soffs[c]);
            const float cm = sred[(5 + c) * 32 + fl] / fmaxf(cntc, 1.f);
            const float d = cm - g;
            between += cntc * d * d;
        }
        between /= Sf;
        float st[6];
        st[0] = between / fmaxf(var, 1e-6f);
        st[1] = nanc / Sf;
        st[2] = (float)__ldg(&g_uniq[b * FF + tile * 32 + fl]) / Sf;
        st[3] = var;
        st[4] = sumabs / Sf;
        st[5] = mx;
#pragma unroll
        for (int k = 0; k < 6; k++) {
            float v = st[k];
            if (!isfinite(v)) v = 0.f;
            sst[fl * 8 + k] = v;
        }
    }
    __syncthreads();

#pragma unroll
    for (int r = 0; r < 8; r++) {
        const int idx = r * 256 + t;
        const int f = idx >> 6, j = idx & 63;
        float z = __ldg(&b1[j]);
#pragma unroll
        for (int i = 0; i < 6; i++) z += sst[f * 8 + i] * __ldg(&w1[i * 64 + j]);
        sh[idx] = z * normcdff(z);           // exact GELU
    }
    __syncthreads();

#pragma unroll
    for (int r = 0; r < 16; r++) {
        const int idx = r * 256 + t;
        const int f = idx >> 7, o = idx & 127;
        float z0 = 0.f, z1 = 0.f;
#pragma unroll 16
        for (int j = 0; j < 64; j += 2) {
            z0 += sh[f * 64 + j]     * sw2[j * 128 + o];
            z1 += sh[f * 64 + j + 1] * sw2[(j + 1) * 128 + o];
        }
        out[((size_t)(b * FF) + tile * 32 + f) * 128 + o] =
            z0 + z1 + __ldg(&b2[o]);
    }
}

// ---------------------------------------------------------------------------
extern "C" void kernel_launch(void* const* d_in, const int* in_sizes, int n_in,
                              void* d_out, int out_size) {
    const float* X  = (const float*)d_in[0];
    const int*   y  = (const int*)d_in[1];
    const float* w1 = (const float*)d_in[2];
    const float* b1 = (const float*)d_in[3];
    const float* w2 = (const float*)d_in[4];
    const float* b2 = (const float*)d_in[5];
    float* out = (float*)d_out;

    cudaFuncSetAttribute(stats_kernel,
                         cudaFuncAttributeMaxDynamicSharedMemorySize, SSMEM);
    cudaFuncSetAttribute(stats_kernel,
                         cudaFuncAttributePreferredSharedMemoryCarveout, 100);
    cudaFuncSetAttribute(uniq_kernel,
                         cudaFuncAttributeMaxDynamicSharedMemorySize, USMEM);
    cudaFuncSetAttribute(uniq_kernel,
                         cudaFuncAttributePreferredSharedMemoryCarveout, 100);
    cudaFuncSetAttribute(mlp_kernel,
                         cudaFuncAttributeMaxDynamicSharedMemorySize, MSMEM);

    prep_kernel<<<BB, 256>>>(y);
    stats_kernel<<<dim3(FF / 4, BB), 256, SSMEM>>>(X);
    uniq_kernel<<<dim3(FF, BB), 256, USMEM>>>();
    mlp_kernel<<<dim3(16, BB), 256, MSMEM>>>(w1, b1, w2, b2, out);
}